// round 4
// baseline (speedup 1.0000x reference)
#include <cuda_runtime.h>

// Problem constants (fixed by the reference)
#define BB 256      // batch
#define NN 2048     // nodes
#define UU 128      // node_units
#define GG 256      // graph_units
#define RCH 16      // row chunks for column-sum partials (128 rows each)

// Scratch (device globals: allocation-free, rewritten fully every launch)
__device__ float g_part[RCH * NN];   // partial column sums
__device__ float g_c[NN];            // column means of adj
__device__ float g_Ap[GG];           // sum_{u: w1>0} w1[u]*w2[u,g]
__device__ float g_Am[GG];           // sum_{u: w1<0} w1[u]*w2[u,g]
__device__ int   g_b1nz;             // 1 iff any b1[u] != 0 (general fallback)

// ---------------------------------------------------------------------------
// Kernel 1: partial column sums of adj. grid(NN/256, RCH), block 256.
// Each block sums a 128-row x 256-col tile; fully coalesced 16 MB read.
// ---------------------------------------------------------------------------
__global__ void colsum_part(const float* __restrict__ adj) {
    const int j  = blockIdx.x * 256 + threadIdx.x;
    const int r0 = blockIdx.y * (NN / RCH);
    float acc = 0.f;
#pragma unroll 8
    for (int i = 0; i < NN / RCH; i++) {
        acc += adj[(r0 + i) * NN + j];
    }
    g_part[blockIdx.y * NN + j] = acc;
}

// ---------------------------------------------------------------------------
// Kernel 2: reduce partials -> column means. grid(NN/256), block 256.
// ---------------------------------------------------------------------------
__global__ void colsum_reduce() {
    const int j = blockIdx.x * 256 + threadIdx.x;
    float s = 0.f;
#pragma unroll
    for (int y = 0; y < RCH; y++) s += g_part[y * NN + j];
    g_c[j] = s * (1.0f / (float)NN);
}

// ---------------------------------------------------------------------------
// Kernel 3: fold w1 through w2 (exploits relu positive homogeneity, b1==0).
// Also computes the b1-nonzero flag for the general fallback path.
// 1 block, 256 threads (one per g).
// ---------------------------------------------------------------------------
__global__ void prep_w(const float* __restrict__ w1,
                       const float* __restrict__ b1,
                       const float* __restrict__ w2) {
    const int g = threadIdx.x;
    float ap = 0.f, am = 0.f;
#pragma unroll 4
    for (int u = 0; u < UU; u++) {
        const float w = w1[u];                // broadcast across the block
        const float v = w2[u * GG + g];       // coalesced
        if (w > 0.f) ap = fmaf(w, v, ap);
        else         am = fmaf(w, v, am);
    }
    g_Ap[g] = ap;
    g_Am[g] = am;

    int nz = (g < UU && b1[g] != 0.f) ? 1 : 0;
    nz = __syncthreads_or(nz);
    if (g == 0) g_b1nz = nz;
}

// ---------------------------------------------------------------------------
// Kernel 4: fused per-batch kernel. grid(BB), block 256 (one thread per g).
//   Phase 0: P[b] = sum_j c[j]*max(nf,0) ; M[b] = sum_j c[j]*min(nf,0)
//   Phase 1: out[b,g] = relu(P*Ap[g] + M*Am[g] + b2[g])
// Fallback (b1 != 0): exact per-u loop + small matmul — never taken here.
// ---------------------------------------------------------------------------
__global__ void fused_out(const float* __restrict__ nf,
                          const float* __restrict__ w1,
                          const float* __restrict__ b1,
                          const float* __restrict__ w2,
                          const float* __restrict__ b2,
                          float* __restrict__ out) {
    const int b   = blockIdx.x;
    const int tid = threadIdx.x;
    const float* __restrict__ row = nf + b * NN;

    // Phase 0: weighted positive/negative sums of this batch row
    float p = 0.f, m = 0.f;
#pragma unroll
    for (int j = tid; j < NN; j += 256) {
        const float v  = row[j];
        const float cj = g_c[j];
        p = fmaf(cj, fmaxf(v, 0.f), p);
        m = fmaf(cj, fminf(v, 0.f), m);
    }
    __shared__ float sp[256];
    __shared__ float sm[256];
    sp[tid] = p;
    sm[tid] = m;
    __syncthreads();
    for (int s = 128; s > 0; s >>= 1) {
        if (tid < s) {
            sp[tid] += sp[tid + s];
            sm[tid] += sm[tid + s];
        }
        __syncthreads();
    }
    const float P = sp[0];
    const float M = sm[0];

    if (!g_b1nz) {
        // Fast path: fully collapsed second layer
        const float o = fmaf(P, g_Ap[tid], fmaf(M, g_Am[tid], b2[tid]));
        out[b * GG + tid] = fmaxf(o, 0.f);
    } else {
        // General path (b1 != 0): exact z[b,u], then small matmul.
        __shared__ float zs[UU];
        if (tid < UU) {
            const float w  = w1[tid];
            const float bb = b1[tid];
            float acc = 0.f;
            for (int j = 0; j < NN; j++) {
                acc = fmaf(g_c[j], fmaxf(fmaf(row[j], w, bb), 0.f), acc);
            }
            zs[tid] = acc;
        }
        __syncthreads();
        float o = b2[tid];
#pragma unroll 4
        for (int u = 0; u < UU; u++) o = fmaf(zs[u], w2[u * GG + tid], o);
        out[b * GG + tid] = fmaxf(o, 0.f);
    }
}

// ---------------------------------------------------------------------------
extern "C" void kernel_launch(void* const* d_in, const int* in_sizes, int n_in,
                              void* d_out, int out_size) {
    const float* nf  = (const float*)d_in[0];   // (B, N)
    const float* adj = (const float*)d_in[1];   // (N, N)
    const float* w1  = (const float*)d_in[2];   // (1, U)
    const float* b1  = (const float*)d_in[3];   // (U,)
    const float* w2  = (const float*)d_in[4];   // (U, G)
    const float* b2  = (const float*)d_in[5];   // (G,)
    float* out = (float*)d_out;                 // (B, G)

    dim3 gs1(NN / 256, RCH);
    colsum_part<<<gs1, 256>>>(adj);
    colsum_reduce<<<NN / 256, 256>>>();
    prep_w<<<1, 256>>>(w1, b1, w2);
    fused_out<<<BB, 256>>>(nf, w1, b1, w2, b2, out);
}

// round 5
// speedup vs baseline: 1.2448x; 1.2448x over previous
#include <cuda_runtime.h>

#define BB 256      // batch
#define NN 2048     // nodes
#define UU 128      // node_units
#define GG 256      // graph_units
#define RCH 128     // row chunks for column-sum partials (16 rows each)

// Scratch (device globals, rewritten fully every launch)
__device__ float4 g_part4[RCH * (NN / 4)];   // partial column sums (1 MB)
__device__ float4 g_c4[NN / 4];              // column means of adj
__device__ float  g_Ap[GG];                  // sum_{u: w1>0} w1[u]*w2[u,g]
__device__ float  g_Am[GG];                  // sum_{u: w1<0} w1[u]*w2[u,g]
__device__ int    g_b1nz;                    // 1 iff any b1[u] != 0

// ---------------------------------------------------------------------------
// Kernel 1: partial column sums of adj, float4. grid(2, RCH), block 256.
// Each block sums a 16-row x 1024-col tile; 16 float4 loads/thread, deep MLP.
// ---------------------------------------------------------------------------
__global__ void colsum_part(const float4* __restrict__ adj4) {
    const int c4 = blockIdx.x * 256 + threadIdx.x;     // 0..511 (float4 col)
    const int r0 = blockIdx.y * (NN / RCH);            // 16 rows per chunk
    float4 acc = make_float4(0.f, 0.f, 0.f, 0.f);
#pragma unroll
    for (int i = 0; i < NN / RCH; i++) {
        const float4 v = adj4[(size_t)(r0 + i) * (NN / 4) + c4];
        acc.x += v.x; acc.y += v.y; acc.z += v.z; acc.w += v.w;
    }
    g_part4[blockIdx.y * (NN / 4) + c4] = acc;
}

// ---------------------------------------------------------------------------
// Kernel 2 (merged): blocks 0..7 reduce partials -> column means;
//                    block 8 folds w1 through w2 and sets the b1 flag.
// grid(9), block 256.
// ---------------------------------------------------------------------------
__global__ void reduce_and_prep(const float* __restrict__ w1,
                                const float* __restrict__ b1,
                                const float* __restrict__ w2) {
    if (blockIdx.x < 8) {
        // Column-mean reduction: col j sums RCH partials.
        const int j = blockIdx.x * 256 + threadIdx.x;  // 0..2047
        const float* part = (const float*)g_part4;
        float s = 0.f;
#pragma unroll 16
        for (int y = 0; y < RCH; y++) s += part[y * NN + j];
        ((float*)g_c4)[j] = s * (1.0f / (float)NN);
    } else {
        // Fold w1 through w2 (relu positive homogeneity, b1 == 0).
        const int g = threadIdx.x;
        float ap = 0.f, am = 0.f;
#pragma unroll 4
        for (int u = 0; u < UU; u++) {
            const float w = w1[u];
            const float v = w2[u * GG + g];
            if (w > 0.f) ap = fmaf(w, v, ap);
            else         am = fmaf(w, v, am);
        }
        g_Ap[g] = ap;
        g_Am[g] = am;
        int nz = (g < UU && b1[g] != 0.f) ? 1 : 0;
        nz = __syncthreads_or(nz);
        if (g == 0) g_b1nz = nz;
    }
}

// ---------------------------------------------------------------------------
// Kernel 3: fused per-batch kernel. grid(BB/2), block 512: two batches per
// block (one wave on 148 SMs). float4 loads, shuffle reduction, fused output.
// ---------------------------------------------------------------------------
__global__ void __launch_bounds__(512, 2)
fused_out(const float* __restrict__ nf,
          const float* __restrict__ w1,
          const float* __restrict__ b1,
          const float* __restrict__ w2,
          const float* __restrict__ b2,
          float* __restrict__ out) {
    const int tid   = threadIdx.x;
    const int local = tid & 255;          // lane within the batch's 256 threads
    const int half  = tid >> 8;           // 0 or 1: which batch of the pair
    const int b     = blockIdx.x * 2 + half;

    const float4* __restrict__ row4 = (const float4*)(nf + (size_t)b * NN);

    // Phase 0: P = sum_j c[j]*max(nf,0), M = sum_j c[j]*min(nf,0)
    float p = 0.f, m = 0.f;
#pragma unroll
    for (int k = 0; k < 2; k++) {
        const int j4 = local + k * 256;   // 0..511
        const float4 v = row4[j4];
        const float4 c = g_c4[j4];
        p = fmaf(c.x, fmaxf(v.x, 0.f), p);
        p = fmaf(c.y, fmaxf(v.y, 0.f), p);
        p = fmaf(c.z, fmaxf(v.z, 0.f), p);
        p = fmaf(c.w, fmaxf(v.w, 0.f), p);
        m = fmaf(c.x, fminf(v.x, 0.f), m);
        m = fmaf(c.y, fminf(v.y, 0.f), m);
        m = fmaf(c.z, fminf(v.z, 0.f), m);
        m = fmaf(c.w, fminf(v.w, 0.f), m);
    }
    // Warp shuffle reduction
#pragma unroll
    for (int o = 16; o > 0; o >>= 1) {
        p += __shfl_xor_sync(0xFFFFFFFFu, p, o);
        m += __shfl_xor_sync(0xFFFFFFFFu, m, o);
    }
    __shared__ float sp[16], sm_[16];
    const int w = tid >> 5;               // warp id 0..15
    if ((tid & 31) == 0) { sp[w] = p; sm_[w] = m; }
    __syncthreads();

    // Each thread sums its batch's 8 warp partials (broadcast smem reads)
    const int base = half * 8;
    float P = 0.f, M = 0.f;
#pragma unroll
    for (int i = 0; i < 8; i++) { P += sp[base + i]; M += sm_[base + i]; }

    if (!g_b1nz) {
        const float o = fmaf(P, g_Ap[local], fmaf(M, g_Am[local], b2[local]));
        out[(size_t)b * GG + local] = fmaxf(o, 0.f);
    } else {
        // General path (b1 != 0): exact z[b,u], then small matmul. Never taken
        // for this dataset (b1 == 0), kept for correctness generality.
        __shared__ float zs[2][UU];
        if (local < UU) {
            const float ww = w1[local];
            const float bb = b1[local];
            const float* row = nf + (size_t)b * NN;
            const float* c   = (const float*)g_c4;
            float acc = 0.f;
            for (int j = 0; j < NN; j++)
                acc = fmaf(c[j], fmaxf(fmaf(row[j], ww, bb), 0.f), acc);
            zs[half][local] = acc;
        }
        __syncthreads();
        float o = b2[local];
#pragma unroll 4
        for (int u = 0; u < UU; u++) o = fmaf(zs[half][u], w2[u * GG + local], o);
        out[(size_t)b * GG + local] = fmaxf(o, 0.f);
    }
}

// ---------------------------------------------------------------------------
extern "C" void kernel_launch(void* const* d_in, const int* in_sizes, int n_in,
                              void* d_out, int out_size) {
    const float* nf  = (const float*)d_in[0];   // (B, N)
    const float* adj = (const float*)d_in[1];   // (N, N)
    const float* w1  = (const float*)d_in[2];   // (1, U)
    const float* b1  = (const float*)d_in[3];   // (U,)
    const float* w2  = (const float*)d_in[4];   // (U, G)
    const float* b2  = (const float*)d_in[5];   // (G,)
    float* out = (float*)d_out;                 // (B, G)

    dim3 gs1(2, RCH);
    colsum_part<<<gs1, 256>>>((const float4*)adj);
    reduce_and_prep<<<9, 256>>>(w1, b1, w2);
    fused_out<<<BB / 2, 512>>>(nf, w1, b1, w2, b2, out);
}

// round 7
// speedup vs baseline: 1.4578x; 1.1711x over previous
#include <cuda_runtime.h>

#define BB 256      // batch
#define NN 2048     // nodes
#define UU 128      // node_units
#define GG 256      // graph_units
#define RCH 128     // partial rows (16 adj rows each)
#define NC4 (NN/4)  // 512 float4 columns

// Scratch (device globals, rewritten fully every launch; counters self-reset)
__device__ float4 g_part4[RCH * NC4];   // partial column sums (1 MB)
__device__ float4 g_c4[NC4];            // column means of adj
__device__ float  g_Ap[GG];             // sum_{u: w1>0} w1[u]*w2[u,g]
__device__ float  g_Am[GG];             // sum_{u: w1<0} w1[u]*w2[u,g]
__device__ int    g_b1nz;               // 1 iff any b1[u] != 0
__device__ int    g_ctr;                // writer arrival counter (zero-init)
__device__ int    g_done;               // reducer completion counter (zero-init)

// ---------------------------------------------------------------------------
// Kernel 1: everything except the per-batch pass.
//   blocks 0..255 : partial column sums of adj (16 rows x 1024 cols each),
//                   explicit 16-deep float4 load batch for true MLP-16.
//   blocks 0..7   : after ALL 256 writers arrive (ticket counter), reduce
//                   their 256-column slice of the partials -> column means.
//   block  256    : fold w1 through w2 (relu pos-homogeneity) + b1 flag.
// All 257 blocks co-resident (launch_bounds(256,2) -> >=296 slots), so the
// spin is deadlock-free. Counters are reset by the last reducer.
// ---------------------------------------------------------------------------
__global__ void __launch_bounds__(256, 2)
colsum_prep(const float4* __restrict__ adj4,
            const float*  __restrict__ w1,
            const float*  __restrict__ b1,
            const float*  __restrict__ w2) {
    const int bid = blockIdx.x;
    const int tid = threadIdx.x;

    if (bid < 256) {
        // ---- partial column sums: 16 rows x 256 f4-cols per block ----
        const int c4 = (bid & 1) * 256 + tid;        // 0..511
        const int r0 = (bid >> 1) * 16;              // row chunk base
        float4 v[16];
#pragma unroll
        for (int i = 0; i < 16; i++)
            v[i] = adj4[(size_t)(r0 + i) * NC4 + c4];
        float4 acc = v[0];
#pragma unroll
        for (int i = 1; i < 16; i++) {
            acc.x += v[i].x; acc.y += v[i].y; acc.z += v[i].z; acc.w += v[i].w;
        }
        g_part4[(size_t)(bid >> 1) * NC4 + c4] = acc;

        __threadfence();
        __syncthreads();
        if (tid == 0) atomicAdd(&g_ctr, 1);

        if (bid < 8) {
            // ---- wait for all 256 writers, then reduce a 256-col slice ----
            if (tid == 0) {
                while (*(volatile int*)&g_ctr < 256) { __nanosleep(32); }
            }
            __syncthreads();
            __threadfence();

            const int j = bid * 256 + tid;           // column 0..2047
            const float* part = (const float*)g_part4;
            float s = 0.f;
#pragma unroll 16
            for (int y = 0; y < RCH; y++) s += part[(size_t)y * NN + j];
            ((float*)g_c4)[j] = s * (1.0f / (float)NN);

            __syncthreads();
            if (tid == 0) {
                const int d = atomicAdd(&g_done, 1);
                if (d == 7) {                        // last reducer: reset state
                    g_ctr  = 0;
                    g_done = 0;
                    __threadfence();
                }
            }
        }
    } else {
        // ---- fold w1 through w2 (b1 == 0 fast path) + b1 flag ----
        const int g = tid;
        float ap = 0.f, am = 0.f;
#pragma unroll 4
        for (int u = 0; u < UU; u++) {
            const float w = w1[u];
            const float x = w2[u * GG + g];
            if (w > 0.f) ap = fmaf(w, x, ap);
            else         am = fmaf(w, x, am);
        }
        g_Ap[g] = ap;
        g_Am[g] = am;
        int nz = (g < UU && b1[g] != 0.f) ? 1 : 0;
        nz = __syncthreads_or(nz);
        if (g == 0) g_b1nz = nz;
    }
}

// ---------------------------------------------------------------------------
// Kernel 2: fused per-batch kernel. grid(BB/2), block 512: two batches per
// block (one wave on 148 SMs). float4 loads, shuffle reduction, fused output.
// ---------------------------------------------------------------------------
__global__ void __launch_bounds__(512, 2)
fused_out(const float* __restrict__ nf,
          const float* __restrict__ w1,
          const float* __restrict__ b1,
          const float* __restrict__ w2,
          const float* __restrict__ b2,
          float* __restrict__ out) {
    const int tid   = threadIdx.x;
    const int local = tid & 255;          // lane within the batch's 256 threads
    const int half  = tid >> 8;           // which batch of the pair
    const int b     = blockIdx.x * 2 + half;

    const float4* __restrict__ row4 = (const float4*)(nf + (size_t)b * NN);

    // Phase 0: P = sum_j c[j]*max(nf,0), M = sum_j c[j]*min(nf,0)
    float p = 0.f, m = 0.f;
#pragma unroll
    for (int k = 0; k < 2; k++) {
        const int j4 = local + k * 256;   // 0..511
        const float4 v = row4[j4];
        const float4 c = g_c4[j4];
        p = fmaf(c.x, fmaxf(v.x, 0.f), p);
        p = fmaf(c.y, fmaxf(v.y, 0.f), p);
        p = fmaf(c.z, fmaxf(v.z, 0.f), p);
        p = fmaf(c.w, fmaxf(v.w, 0.f), p);
        m = fmaf(c.x, fminf(v.x, 0.f), m);
        m = fmaf(c.y, fminf(v.y, 0.f), m);
        m = fmaf(c.z, fminf(v.z, 0.f), m);
        m = fmaf(c.w, fminf(v.w, 0.f), m);
    }
#pragma unroll
    for (int o = 16; o > 0; o >>= 1) {
        p += __shfl_xor_sync(0xFFFFFFFFu, p, o);
        m += __shfl_xor_sync(0xFFFFFFFFu, m, o);
    }
    __shared__ float sp[16], sm_[16];
    const int w = tid >> 5;               // warp id 0..15
    if ((tid & 31) == 0) { sp[w] = p; sm_[w] = m; }
    __syncthreads();

    const int base = half * 8;
    float P = 0.f, M = 0.f;
#pragma unroll
    for (int i = 0; i < 8; i++) { P += sp[base + i]; M += sm_[base + i]; }

    if (!g_b1nz) {
        const float o = fmaf(P, g_Ap[local], fmaf(M, g_Am[local], b2[local]));
        out[(size_t)b * GG + local] = fmaxf(o, 0.f);
    } else {
        // General path (b1 != 0): exact z[b,u], then small matmul. Never taken
        // for this dataset (b1 == 0); kept for correctness generality.
        __shared__ float zs[2][UU];
        if (local < UU) {
            const float ww = w1[local];
            const float bb = b1[local];
            const float* row = nf + (size_t)b * NN;
            const float* c   = (const float*)g_c4;
            float acc = 0.f;
            for (int j = 0; j < NN; j++)
                acc = fmaf(c[j], fmaxf(fmaf(row[j], ww, bb), 0.f), acc);
            zs[half][local] = acc;
        }
        __syncthreads();
        float o = b2[local];
#pragma unroll 4
        for (int u = 0; u < UU; u++) o = fmaf(zs[half][u], w2[u * GG + local], o);
        out[(size_t)b * GG + local] = fmaxf(o, 0.f);
    }
}

// ---------------------------------------------------------------------------
extern "C" void kernel_launch(void* const* d_in, const int* in_sizes, int n_in,
                              void* d_out, int out_size) {
    const float* nf  = (const float*)d_in[0];   // (B, N)
    const float* adj = (const float*)d_in[1];   // (N, N)
    const float* w1  = (const float*)d_in[2];   // (1, U)
    const float* b1  = (const float*)d_in[3];   // (U,)
    const float* w2  = (const float*)d_in[4];   // (U, G)
    const float* b2  = (const float*)d_in[5];   // (G,)
    float* out = (float*)d_out;                 // (B, G)

    colsum_prep<<<257, 256>>>((const float4*)adj, w1, b1, w2);
    fused_out<<<BB / 2, 512>>>(nf, w1, b1, w2, b2, out);
}